// round 1
// baseline (speedup 1.0000x reference)
#include <cuda_runtime.h>
#include <math.h>

#define EMBED 768
#define HEADS 12
#define HD    64
#define MLPD  3072
#define BATCH 4
#define SEQ   1024
#define ROWS  (BATCH*SEQ)   // 4096
#define QKVW  (3*EMBED)     // 2304

// ---------------- scratch (static device allocations, per harness rules) ----
__device__ float g_h   [ROWS*EMBED];   // LN1 output
__device__ float g_qkv [ROWS*QKVW];    // qkv projections
__device__ float g_attn[ROWS*EMBED];   // attention output (pre out-proj)
__device__ float g_x2  [ROWS*EMBED];   // x + h + attn_proj
__device__ float g_h2  [ROWS*EMBED];   // LN2 output
__device__ float g_mid [ROWS*MLPD];    // gelu(h2@w1+b1)

// ---------------- LayerNorm: one block per row of 768 ----------------------
__global__ __launch_bounds__(256) void ln_kernel(const float* __restrict__ x,
                                                 const float* __restrict__ g,
                                                 const float* __restrict__ b,
                                                 float* __restrict__ out)
{
    const int row = blockIdx.x;
    const int t = threadIdx.x;
    const float* xr = x + (size_t)row * EMBED;
    float v0 = xr[t], v1 = xr[t + 256], v2 = xr[t + 512];
    float s  = v0 + v1 + v2;
    float sq = v0*v0 + v1*v1 + v2*v2;
    #pragma unroll
    for (int off = 16; off; off >>= 1) {
        s  += __shfl_xor_sync(0xffffffffu, s,  off);
        sq += __shfl_xor_sync(0xffffffffu, sq, off);
    }
    __shared__ float red[16];
    const int w = t >> 5;
    if ((t & 31) == 0) { red[w] = s; red[8 + w] = sq; }
    __syncthreads();
    float tot = 0.f, totq = 0.f;
    #pragma unroll
    for (int i = 0; i < 8; i++) { tot += red[i]; totq += red[8 + i]; }
    const float mu   = tot  * (1.f / 768.f);
    float var        = totq * (1.f / 768.f) - mu * mu;
    const float rstd = rsqrtf(fmaxf(var, 0.f) + 1e-5f);
    float* orow = out + (size_t)row * EMBED;
    orow[t]       = (v0 - mu) * rstd * g[t]       + b[t];
    orow[t + 256] = (v1 - mu) * rstd * g[t + 256] + b[t + 256];
    orow[t + 512] = (v2 - mu) * rstd * g[t + 512] + b[t + 512];
}

// ---------------- SGEMM: 128x128x8 tile, 8x8 per thread, fused epilogues ----
// EPI 0: C = acc
// EPI 1: C = acc + bias[col] + add1[idx] + add2[idx]
// EPI 2: C = gelu_exact(acc + bias[col])
// EPI 3: C = acc + bias[col] + add1[idx]
template<int EPI>
__global__ __launch_bounds__(256) void sgemm(const float* __restrict__ A,
                                             const float* __restrict__ B,
                                             const float* __restrict__ bias,
                                             const float* __restrict__ add1,
                                             const float* __restrict__ add2,
                                             float* __restrict__ C,
                                             int M, int N, int K)
{
    __shared__ float As[8][132];   // transposed A tile, padded vs bank conflicts
    __shared__ float Bs[8][128];
    const int tid = threadIdx.x;
    const int tx = tid & 15;        // output col group
    const int ty = tid >> 4;        // output row group
    const int rowBase = blockIdx.y * 128;
    const int colBase = blockIdx.x * 128;
    const int aRow = tid >> 1;              // 0..127
    const int aCol = (tid & 1) << 2;        // 0 or 4
    const int bRow = tid >> 5;              // 0..7
    const int bCol = (tid & 31) << 2;       // 0..124

    const float* Abase = A + (size_t)(rowBase + aRow) * K + aCol;
    const float* Bbase = B + (size_t)bRow * N + colBase + bCol;

    float acc[8][8];
    #pragma unroll
    for (int i = 0; i < 8; i++)
        #pragma unroll
        for (int j = 0; j < 8; j++) acc[i][j] = 0.f;

    for (int k0 = 0; k0 < K; k0 += 8) {
        const float4 av = *(const float4*)(Abase + k0);
        const float4 bv = *(const float4*)(Bbase + (size_t)k0 * N);
        __syncthreads();
        As[aCol + 0][aRow] = av.x;
        As[aCol + 1][aRow] = av.y;
        As[aCol + 2][aRow] = av.z;
        As[aCol + 3][aRow] = av.w;
        *(float4*)&Bs[bRow][bCol] = bv;
        __syncthreads();
        #pragma unroll
        for (int kk = 0; kk < 8; kk++) {
            const float4 a0 = *(const float4*)&As[kk][ty * 8];
            const float4 a1 = *(const float4*)&As[kk][ty * 8 + 4];
            const float4 b0 = *(const float4*)&Bs[kk][tx * 8];
            const float4 b1 = *(const float4*)&Bs[kk][tx * 8 + 4];
            const float ra[8] = {a0.x,a0.y,a0.z,a0.w,a1.x,a1.y,a1.z,a1.w};
            const float rb[8] = {b0.x,b0.y,b0.z,b0.w,b1.x,b1.y,b1.z,b1.w};
            #pragma unroll
            for (int i = 0; i < 8; i++)
                #pragma unroll
                for (int j = 0; j < 8; j++)
                    acc[i][j] += ra[i] * rb[j];
        }
    }

    #pragma unroll
    for (int i = 0; i < 8; i++) {
        const int r = rowBase + ty * 8 + i;
        #pragma unroll
        for (int j = 0; j < 8; j++) {
            const int c = colBase + tx * 8 + j;
            const size_t idx = (size_t)r * N + c;
            float v = acc[i][j];
            if (EPI == 1) v += bias[c] + add1[idx] + add2[idx];
            if (EPI == 2) { v += bias[c]; v = 0.5f * v * (1.f + erff(v * 0.70710678118654752f)); }
            if (EPI == 3) v += bias[c] + add1[idx];
            C[idx] = v;
        }
    }
}

// ---------------- Flash attention: 64 queries/block, 32-key tiles, fp32 -----
// grid = (SEQ/64, B*HEADS), 256 threads. Thread t: query row = t/4, quad lane
// tx = t%3..  Per key tile each thread scores keys {c*4+tx}, owns O columns
// [tx*16, tx*16+16).
__global__ __launch_bounds__(256) void attn_kernel(const float* __restrict__ qkv,
                                                   float* __restrict__ out)
{
    __shared__ float sQ[64][68];
    __shared__ float sK[32][68];
    __shared__ float sV[32][68];
    __shared__ float sP[64][36];

    const int tid = threadIdx.x;
    const int qt  = blockIdx.x;
    const int b   = blockIdx.y / HEADS;
    const int h   = blockIdx.y % HEADS;
    const float* base = qkv + (size_t)b * SEQ * QKVW;
    const int qoff = h * HD;
    const int koff = EMBED + h * HD;
    const int voff = 2 * EMBED + h * HD;

    // load Q tile (64x64), pre-scale by 1/sqrt(D) = 0.125
    #pragma unroll
    for (int i = 0; i < 4; i++) {
        const int idx = i * 256 + tid;     // 0..1023 float4s
        const int r = idx >> 4;
        const int c = (idx & 15) << 2;
        float4 v = *(const float4*)(base + (size_t)(qt * 64 + r) * QKVW + qoff + c);
        v.x *= 0.125f; v.y *= 0.125f; v.z *= 0.125f; v.w *= 0.125f;
        *(float4*)&sQ[r][c] = v;
    }

    const int row = tid >> 2;   // 0..63
    const int tx  = tid & 3;    // 0..3
    float m = -1e30f, l = 0.f;
    float o[16];
    #pragma unroll
    for (int c = 0; c < 16; c++) o[c] = 0.f;

    for (int j0 = 0; j0 < SEQ; j0 += 32) {
        __syncthreads();   // previous tile fully consumed (also covers Q on iter 0... loaded before)
        #pragma unroll
        for (int i = 0; i < 2; i++) {
            const int idx = i * 256 + tid; // 0..511 float4s
            const int r = idx >> 4;
            const int c = (idx & 15) << 2;
            const size_t g = (size_t)(j0 + r) * QKVW;
            *(float4*)&sK[r][c] = *(const float4*)(base + g + koff + c);
            *(float4*)&sV[r][c] = *(const float4*)(base + g + voff + c);
        }
        __syncthreads();

        // scores for this thread's 8 keys
        float s[8];
        #pragma unroll
        for (int c = 0; c < 8; c++) s[c] = 0.f;
        #pragma unroll
        for (int d4 = 0; d4 < 16; d4++) {
            const float4 qv = *(const float4*)&sQ[row][d4 * 4];
            #pragma unroll
            for (int c = 0; c < 8; c++) {
                const float4 kv = *(const float4*)&sK[c * 4 + tx][d4 * 4];
                s[c] += qv.x*kv.x + qv.y*kv.y + qv.z*kv.z + qv.w*kv.w;
            }
        }

        // online softmax across the row quad
        float tmax = s[0];
        #pragma unroll
        for (int c = 1; c < 8; c++) tmax = fmaxf(tmax, s[c]);
        tmax = fmaxf(tmax, __shfl_xor_sync(0xffffffffu, tmax, 1));
        tmax = fmaxf(tmax, __shfl_xor_sync(0xffffffffu, tmax, 2));
        const float mnew  = fmaxf(m, tmax);
        const float alpha = __expf(m - mnew);
        float psum = 0.f;
        #pragma unroll
        for (int c = 0; c < 8; c++) {
            const float p = __expf(s[c] - mnew);
            sP[row][c * 4 + tx] = p;
            psum += p;
        }
        psum += __shfl_xor_sync(0xffffffffu, psum, 1);
        psum += __shfl_xor_sync(0xffffffffu, psum, 2);
        l = l * alpha + psum;
        m = mnew;
        #pragma unroll
        for (int c = 0; c < 16; c++) o[c] *= alpha;
        __syncwarp();   // sP visible within the row quad (same warp)

        // O += P @ V for this tile
        #pragma unroll
        for (int key = 0; key < 32; key++) {
            const float p = sP[row][key];
            const float4 v0 = *(const float4*)&sV[key][tx * 16];
            const float4 v1 = *(const float4*)&sV[key][tx * 16 + 4];
            const float4 v2 = *(const float4*)&sV[key][tx * 16 + 8];
            const float4 v3 = *(const float4*)&sV[key][tx * 16 + 12];
            o[0]  += p * v0.x; o[1]  += p * v0.y; o[2]  += p * v0.z; o[3]  += p * v0.w;
            o[4]  += p * v1.x; o[5]  += p * v1.y; o[6]  += p * v1.z; o[7]  += p * v1.w;
            o[8]  += p * v2.x; o[9]  += p * v2.y; o[10] += p * v2.z; o[11] += p * v2.w;
            o[12] += p * v3.x; o[13] += p * v3.y; o[14] += p * v3.z; o[15] += p * v3.w;
        }
    }

    const float rl = 1.f / l;
    float* op = out + ((size_t)(b * SEQ + qt * 64 + row)) * EMBED + h * HD + tx * 16;
    #pragma unroll
    for (int c4 = 0; c4 < 4; c4++) {
        float4 v = make_float4(o[c4*4]*rl, o[c4*4+1]*rl, o[c4*4+2]*rl, o[c4*4+3]*rl);
        *(float4*)(op + c4 * 4) = v;
    }
}

// ---------------- host launcher --------------------------------------------
extern "C" void kernel_launch(void* const* d_in, const int* in_sizes, int n_in,
                              void* d_out, int out_size)
{
    const float* x     = (const float*)d_in[0];
    const float* ln1_g = (const float*)d_in[1];
    const float* ln1_b = (const float*)d_in[2];
    const float* w_qkv = (const float*)d_in[3];
    const float* w_out = (const float*)d_in[4];
    const float* b_out = (const float*)d_in[5];
    const float* ln2_g = (const float*)d_in[6];
    const float* ln2_b = (const float*)d_in[7];
    const float* w1    = (const float*)d_in[8];
    const float* b1    = (const float*)d_in[9];
    const float* w2    = (const float*)d_in[10];
    const float* b2    = (const float*)d_in[11];
    float* out = (float*)d_out;

    float *h, *qkv, *attn, *x2, *h2, *mid;
    cudaGetSymbolAddress((void**)&h,    g_h);
    cudaGetSymbolAddress((void**)&qkv,  g_qkv);
    cudaGetSymbolAddress((void**)&attn, g_attn);
    cudaGetSymbolAddress((void**)&x2,   g_x2);
    cudaGetSymbolAddress((void**)&h2,   g_h2);
    cudaGetSymbolAddress((void**)&mid,  g_mid);

    // 1) h = LN1(x)
    ln_kernel<<<ROWS, 256>>>(x, ln1_g, ln1_b, h);
    // 2) qkv = h @ w_qkv
    sgemm<0><<<dim3(QKVW/128, ROWS/128), 256>>>(h, w_qkv, nullptr, nullptr, nullptr,
                                                qkv, ROWS, QKVW, EMBED);
    // 3) attn = softmax(qk^T/sqrt(d)) v   (flash, fused)
    attn_kernel<<<dim3(SEQ/64, BATCH*HEADS), 256>>>(qkv, attn);
    // 4) x2 = x + h + (attn @ w_out + b_out)
    sgemm<1><<<dim3(EMBED/128, ROWS/128), 256>>>(attn, w_out, b_out, x, h,
                                                 x2, ROWS, EMBED, EMBED);
    // 5) h2 = LN2(x2)
    ln_kernel<<<ROWS, 256>>>(x2, ln2_g, ln2_b, h2);
    // 6) mid = gelu(h2 @ w1 + b1)   (exact gelu)
    sgemm<2><<<dim3(MLPD/128, ROWS/128), 256>>>(h2, w1, b1, nullptr, nullptr,
                                                mid, ROWS, MLPD, EMBED);
    // 7) out = x2 + (mid @ w2 + b2)
    sgemm<3><<<dim3(EMBED/128, ROWS/128), 256>>>(mid, w2, b2, x2, nullptr,
                                                 out, ROWS, EMBED, MLPD);
}

// round 3
// speedup vs baseline: 1.7588x; 1.7588x over previous
#include <cuda_runtime.h>
#include <cuda_bf16.h>
#include <math.h>
#include <stdint.h>

#define EMBED 768
#define HEADS 12
#define HD    64
#define MLPD  3072
#define BATCH 4
#define SEQ   1024
#define ROWS  (BATCH*SEQ)
#define QKVW  (3*EMBED)
#define BH    (BATCH*HEADS)

typedef __nv_bfloat16 bf16;

// ------------------------- scratch ------------------------------------------
__device__ float g_h32 [ROWS*EMBED];
__device__ bf16  g_h_hi[ROWS*EMBED],  g_h_lo[ROWS*EMBED];
__device__ bf16  g_wqkvT_hi[QKVW*EMBED], g_wqkvT_lo[QKVW*EMBED];
__device__ bf16  g_woutT_hi[EMBED*EMBED], g_woutT_lo[EMBED*EMBED];
__device__ bf16  g_w1T_hi[MLPD*EMBED],  g_w1T_lo[MLPD*EMBED];
__device__ bf16  g_w2T_hi[EMBED*MLPD],  g_w2T_lo[EMBED*MLPD];
__device__ bf16  g_qkv_hi[ROWS*QKVW],   g_qkv_lo[ROWS*QKVW];
__device__ float g_S[(size_t)BH*SEQ*SEQ];
__device__ bf16  g_P_hi[(size_t)BH*SEQ*SEQ], g_P_lo[(size_t)BH*SEQ*SEQ];
__device__ bf16  g_attn_hi[ROWS*EMBED], g_attn_lo[ROWS*EMBED];
__device__ float g_x2[ROWS*EMBED];
__device__ bf16  g_h2_hi[ROWS*EMBED],  g_h2_lo[ROWS*EMBED];
__device__ bf16  g_mid_hi[ROWS*MLPD],  g_mid_lo[ROWS*MLPD];

// ------------------------- helpers ------------------------------------------
__device__ __forceinline__ uint32_t smem_u32(const void* p){
    uint32_t a;
    asm("{ .reg .u64 t; cvta.to.shared.u64 t, %1; cvt.u32.u64 %0, t; }" : "=r"(a) : "l"(p));
    return a;
}
__device__ __forceinline__ void split_bf(float v, bf16& h, bf16& l){
    h = __float2bfloat16(v);
    l = __float2bfloat16(v - __bfloat162float(h));
}
__device__ __forceinline__ void cp16(uint32_t dst, const void* src){
    asm volatile("cp.async.cg.shared.global [%0], [%1], 16;" :: "r"(dst), "l"(src));
}
__device__ __forceinline__ void ldsm4(uint32_t* r, uint32_t a){
    asm volatile("ldmatrix.sync.aligned.m8n8.x4.shared.b16 {%0,%1,%2,%3}, [%4];"
        : "=r"(r[0]),"=r"(r[1]),"=r"(r[2]),"=r"(r[3]) : "r"(a));
}
__device__ __forceinline__ void ldsm2(uint32_t* r, uint32_t a){
    asm volatile("ldmatrix.sync.aligned.m8n8.x2.shared.b16 {%0,%1}, [%2];"
        : "=r"(r[0]),"=r"(r[1]) : "r"(a));
}
__device__ __forceinline__ void mma16816(float* c, const uint32_t* a, const uint32_t* b){
    asm volatile("mma.sync.aligned.m16n8k16.row.col.f32.bf16.bf16.f32 "
        "{%0,%1,%2,%3}, {%4,%5,%6,%7}, {%8,%9}, {%0,%1,%2,%3};"
        : "+f"(c[0]),"+f"(c[1]),"+f"(c[2]),"+f"(c[3])
        : "r"(a[0]),"r"(a[1]),"r"(a[2]),"r"(a[3]), "r"(b[0]),"r"(b[1]));
}

// ------------------------- weight transpose + split -------------------------
__global__ void tconv(const float* __restrict__ W, bf16* __restrict__ Thi, bf16* __restrict__ Tlo,
                      int K, int N)
{
    __shared__ float s[32][33];
    const int n0 = blockIdx.x * 32, k0 = blockIdx.y * 32;
    const int tx = threadIdx.x, ty = threadIdx.y;
    #pragma unroll
    for (int i = 0; i < 4; i++)
        s[ty + i*8][tx] = W[(size_t)(k0 + ty + i*8) * N + n0 + tx];
    __syncthreads();
    #pragma unroll
    for (int i = 0; i < 4; i++) {
        const int n = ty + i*8;
        float v = s[tx][n];
        bf16 h, l; split_bf(v, h, l);
        const size_t o = (size_t)(n0 + n) * K + k0 + tx;
        Thi[o] = h; Tlo[o] = l;
    }
}

// ------------------------- LayerNorm ----------------------------------------
__global__ __launch_bounds__(256) void ln_kernel(const float* __restrict__ x,
                                                 const float* __restrict__ g,
                                                 const float* __restrict__ b,
                                                 float* __restrict__ out32,
                                                 bf16* __restrict__ ohi,
                                                 bf16* __restrict__ olo)
{
    const int row = blockIdx.x;
    const int t = threadIdx.x;
    const float* xr = x + (size_t)row * EMBED;
    float v0 = xr[t], v1 = xr[t+256], v2 = xr[t+512];
    float s = v0+v1+v2, sq = v0*v0+v1*v1+v2*v2;
    #pragma unroll
    for (int off = 16; off; off >>= 1) {
        s  += __shfl_xor_sync(0xffffffffu, s,  off);
        sq += __shfl_xor_sync(0xffffffffu, sq, off);
    }
    __shared__ float red[16];
    const int w = t >> 5;
    if ((t & 31) == 0) { red[w] = s; red[8+w] = sq; }
    __syncthreads();
    float tot = 0.f, totq = 0.f;
    #pragma unroll
    for (int i = 0; i < 8; i++) { tot += red[i]; totq += red[8+i]; }
    const float mu = tot * (1.f/768.f);
    const float var = totq * (1.f/768.f) - mu*mu;
    const float rstd = rsqrtf(fmaxf(var, 0.f) + 1e-5f);
    const size_t o = (size_t)row * EMBED;
    #pragma unroll
    for (int i = 0; i < 3; i++) {
        const int c = t + i*256;
        const float v = (i==0?v0:(i==1?v1:v2));
        const float y = (v - mu) * rstd * g[c] + b[c];
        if (out32) out32[o + c] = y;
        bf16 h, l; split_bf(y, h, l);
        ohi[o + c] = h; olo[o + c] = l;
    }
}

// ------------------------- softmax (rows of 1024) ---------------------------
__global__ __launch_bounds__(256) void softmax_k(const float* __restrict__ S,
                                                 bf16* __restrict__ Phi,
                                                 bf16* __restrict__ Plo)
{
    const size_t row = blockIdx.x;
    const float* r = S + row * SEQ;
    const int t = threadIdx.x;
    float v[4];
    #pragma unroll
    for (int i = 0; i < 4; i++) v[i] = r[t + i*256] * 0.125f;
    float mx = fmaxf(fmaxf(v[0], v[1]), fmaxf(v[2], v[3]));
    #pragma unroll
    for (int off = 16; off; off >>= 1) mx = fmaxf(mx, __shfl_xor_sync(0xffffffffu, mx, off));
    __shared__ float red[16];
    const int w = t >> 5;
    if ((t & 31) == 0) red[w] = mx;
    __syncthreads();
    float bm = red[0];
    #pragma unroll
    for (int i = 1; i < 8; i++) bm = fmaxf(bm, red[i]);
    float e[4], s = 0.f;
    #pragma unroll
    for (int i = 0; i < 4; i++) { e[i] = __expf(v[i] - bm); s += e[i]; }
    #pragma unroll
    for (int off = 16; off; off >>= 1) s += __shfl_xor_sync(0xffffffffu, s, off);
    if ((t & 31) == 0) red[8+w] = s;
    __syncthreads();
    float tot = 0.f;
    #pragma unroll
    for (int i = 0; i < 8; i++) tot += red[8+i];
    const float rl = 1.f / tot;
    #pragma unroll
    for (int i = 0; i < 4; i++) {
        bf16 h, l; split_bf(e[i] * rl, h, l);
        Phi[row*SEQ + t + i*256] = h;
        Plo[row*SEQ + t + i*256] = l;
    }
}

// ------------------------- mma.sync hi/lo-split GEMM ------------------------
// C[m][n] = sum_k A[m][k]*B[n][k]; A/B as bf16 hi/lo planes; 3 MMAs (hh+hl+lh).
// Block 128xNT, 8 warps (2 m x 4 n), warp tile 64 x NT/4, K-chunk 32, dbl-buf.
// EPI 0: f32   1: hi/lo split   2: f32+bias+add1+add2   3: split(gelu(+bias))
// EPI 4: f32+bias+add1
template<int EPI, bool TRANSB, int NT>
__global__ void __launch_bounds__(256) gemm_mma(
    const bf16* __restrict__ Ahi, const bf16* __restrict__ Alo, int lda, int adiv, size_t aouter, size_t ainner,
    const bf16* __restrict__ Bhi, const bf16* __restrict__ Blo, int ldb, int bdiv, size_t bouter, size_t binner,
    float* __restrict__ C, bf16* __restrict__ Chi, bf16* __restrict__ Clo, int ldc, int cdiv, size_t couter, size_t cinner,
    const float* __restrict__ bias, const float* __restrict__ add1, const float* __restrict__ add2,
    int K)
{
    constexpr int RS  = 80;              // smem row stride (bytes): conflict-free
    constexpr int SA  = 128 * RS;        // one A plane
    constexpr int SBp = NT * RS;         // one B plane
    constexpr int BUF = 2*SA + 2*SBp;
    constexpr int NTILES = NT / 32;      // 8-col n-tiles per warp

    extern __shared__ char sm[];
    const uint32_t smb = smem_u32(sm);

    const int tid  = threadIdx.x;
    const int wid  = tid >> 5, lane = tid & 31;
    const int warp_m = wid & 1, warp_n = wid >> 1;
    const int bz = blockIdx.z;
    const size_t offA = (size_t)(bz / adiv) * aouter + (size_t)(bz % adiv) * ainner;
    const size_t offB = (size_t)(bz / bdiv) * bouter + (size_t)(bz % bdiv) * binner;
    const size_t offC = (size_t)(bz / cdiv) * couter + (size_t)(bz % cdiv) * cinner;
    const int rowBase = blockIdx.y * 128;
    const int colBase = blockIdx.x * NT;

    float acc[4][NTILES][4];
    #pragma unroll
    for (int mt = 0; mt < 4; mt++)
        #pragma unroll
        for (int nt = 0; nt < NTILES; nt++)
            #pragma unroll
            for (int i = 0; i < 4; i++) acc[mt][nt][i] = 0.f;

    auto load_chunk = [&](int c) {
        const int buf = c & 1;
        const uint32_t st = smb + buf*BUF;
        const int k0 = c * 32;
        // A: 2 planes x 128 rows x 4 x 16B
        #pragma unroll
        for (int i = 0; i < 4; i++) {
            const int t = tid + i*256;
            const int plane = t >> 9, rr = (t >> 2) & 127, cg = t & 3;
            const bf16* src = (plane ? Alo : Ahi) + offA + (size_t)(rowBase + rr) * lda + k0 + cg*8;
            cp16(st + plane*SA + rr*RS + cg*16, src);
        }
        if (!TRANSB) {
            #pragma unroll
            for (int i = 0; i < NT/32; i++) {       // 2*NT*4 ops / 256 thr
                const int t = tid + i*256;
                const int plane = t / (NT*4), r2 = t % (NT*4), rr = r2 >> 2, cg = r2 & 3;
                const bf16* src = (plane ? Blo : Bhi) + offB + (size_t)(colBase + rr) * ldb + k0 + cg*8;
                cp16(st + 2*SA + plane*SBp + rr*RS + cg*16, src);
            }
        } else {
            // B[n][k] <- Bsrc[k][n]; NT==64: 2 planes x 32 k x 8 groups
            #pragma unroll
            for (int i = 0; i < 2; i++) {
                const int t = tid + i*256;
                const int plane = t >> 8, r2 = t & 255;
                const int kk = r2 >> 3, n8 = r2 & 7;
                const bf16* src = (plane ? Blo : Bhi) + offB + (size_t)(k0 + kk) * ldb + n8*8;
                union { float4 f; unsigned short u[8]; } u;
                u.f = *(const float4*)src;
                char* basep = sm + buf*BUF + 2*SA + plane*SBp;
                #pragma unroll
                for (int j = 0; j < 8; j++)
                    *(unsigned short*)(basep + (n8*8 + j)*RS + kk*2) = u.u[j];
            }
        }
        asm volatile("cp.async.commit_group;");
    };

    load_chunk(0);
    const int NC = K / 32;
    for (int c = 0; c < NC; ++c) {
        asm volatile("cp.async.wait_group 0;" ::: "memory");
        __syncthreads();
        if (c + 1 < NC) load_chunk(c + 1);      // overlaps compute below

        const uint32_t st = smb + (c & 1)*BUF;
        #pragma unroll
        for (int ks = 0; ks < 2; ks++) {
            uint32_t bh[NTILES][2], bl[NTILES][2];
            #pragma unroll
            for (int nt = 0; nt < NTILES; nt++) {
                const int row = warp_n*(NT/4) + nt*8 + (lane & 7);
                const int kb  = ks*32 + ((lane >> 3) & 1)*16;
                const uint32_t ad = st + 2*SA + row*RS + kb;
                ldsm2(bh[nt], ad);
                ldsm2(bl[nt], ad + SBp);
            }
            #pragma unroll
            for (int mt = 0; mt < 4; mt++) {
                const int row = warp_m*64 + mt*16 + (lane & 15);
                const int kb  = ks*32 + (lane >> 4)*16;
                const uint32_t aad = st + row*RS + kb;
                uint32_t ah[4], al[4];
                ldsm4(ah, aad);
                ldsm4(al, aad + SA);
                #pragma unroll
                for (int nt = 0; nt < NTILES; nt++) {
                    mma16816(acc[mt][nt], ah, bh[nt]);
                    mma16816(acc[mt][nt], ah, bl[nt]);
                    mma16816(acc[mt][nt], al, bh[nt]);
                }
            }
        }
    }

    // ---- epilogue: direct fragment-layout stores ---------------------------
    #pragma unroll
    for (int mt = 0; mt < 4; mt++) {
        #pragma unroll
        for (int nt = 0; nt < NTILES; nt++) {
            const int gr0 = rowBase + warp_m*64 + mt*16 + (lane >> 2);
            const int gc  = colBase + warp_n*(NT/4) + nt*8 + (lane & 3)*2;
            #pragma unroll
            for (int half = 0; half < 2; half++) {
                const int gr = gr0 + half*8;
                const size_t idx = offC + (size_t)gr * ldc + gc;
                float v0 = acc[mt][nt][half*2 + 0];
                float v1 = acc[mt][nt][half*2 + 1];
                if (EPI == 0) {
                    *(float2*)(C + idx) = make_float2(v0, v1);
                } else if (EPI == 2) {
                    v0 += bias[gc+0] + add1[idx+0] + add2[idx+0];
                    v1 += bias[gc+1] + add1[idx+1] + add2[idx+1];
                    *(float2*)(C + idx) = make_float2(v0, v1);
                } else if (EPI == 4) {
                    v0 += bias[gc+0] + add1[idx+0];
                    v1 += bias[gc+1] + add1[idx+1];
                    *(float2*)(C + idx) = make_float2(v0, v1);
                } else {
                    if (EPI == 3) {
                        v0 += bias[gc+0];
                        v1 += bias[gc+1];
                        v0 = 0.5f * v0 * (1.f + erff(v0 * 0.70710678118654752f));
                        v1 = 0.5f * v1 * (1.f + erff(v1 * 0.70710678118654752f));
                    }
                    bf16 h0, l0, h1, l1;
                    split_bf(v0, h0, l0);
                    split_bf(v1, h1, l1);
                    *(__nv_bfloat162*)(Chi + idx) = __halves2bfloat162(h0, h1);
                    *(__nv_bfloat162*)(Clo + idx) = __halves2bfloat162(l0, l1);
                }
            }
        }
    }
}

// ------------------------- host ---------------------------------------------
extern "C" void kernel_launch(void* const* d_in, const int* in_sizes, int n_in,
                              void* d_out, int out_size)
{
    const float* x     = (const float*)d_in[0];
    const float* ln1_g = (const float*)d_in[1];
    const float* ln1_b = (const float*)d_in[2];
    const float* w_qkv = (const float*)d_in[3];
    const float* w_out = (const float*)d_in[4];
    const float* b_out = (const float*)d_in[5];
    const float* ln2_g = (const float*)d_in[6];
    const float* ln2_b = (const float*)d_in[7];
    const float* w1    = (const float*)d_in[8];
    const float* b1    = (const float*)d_in[9];
    const float* w2    = (const float*)d_in[10];
    const float* b2    = (const float*)d_in[11];
    float* out = (float*)d_out;

    float *h32, *S, *x2;
    bf16 *h_hi,*h_lo,*wqkvT_hi,*wqkvT_lo,*woutT_hi,*woutT_lo,*w1T_hi,*w1T_lo,*w2T_hi,*w2T_lo;
    bf16 *qkv_hi,*qkv_lo,*P_hi,*P_lo,*attn_hi,*attn_lo,*h2_hi,*h2_lo,*mid_hi,*mid_lo;
    cudaGetSymbolAddress((void**)&h32, g_h32);
    cudaGetSymbolAddress((void**)&h_hi, g_h_hi);       cudaGetSymbolAddress((void**)&h_lo, g_h_lo);
    cudaGetSymbolAddress((void**)&wqkvT_hi, g_wqkvT_hi); cudaGetSymbolAddress((void**)&wqkvT_lo, g_wqkvT_lo);
    cudaGetSymbolAddress((void**)&woutT_hi, g_woutT_hi); cudaGetSymbolAddress((void**)&woutT_lo, g_woutT_lo);
    cudaGetSymbolAddress((void**)&w1T_hi, g_w1T_hi);   cudaGetSymbolAddress((void**)&w1T_lo, g_w1T_lo);
    cudaGetSymbolAddress((void**)&w2T_hi, g_w2T_hi);   cudaGetSymbolAddress((void**)&w2T_lo, g_w2T_lo);
    cudaGetSymbolAddress((void**)&qkv_hi, g_qkv_hi);   cudaGetSymbolAddress((void**)&qkv_lo, g_qkv_lo);
    cudaGetSymbolAddress((void**)&S, g_S);
    cudaGetSymbolAddress((void**)&P_hi, g_P_hi);       cudaGetSymbolAddress((void**)&P_lo, g_P_lo);
    cudaGetSymbolAddress((void**)&attn_hi, g_attn_hi); cudaGetSymbolAddress((void**)&attn_lo, g_attn_lo);
    cudaGetSymbolAddress((void**)&x2, g_x2);
    cudaGetSymbolAddress((void**)&h2_hi, g_h2_hi);     cudaGetSymbolAddress((void**)&h2_lo, g_h2_lo);
    cudaGetSymbolAddress((void**)&mid_hi, g_mid_hi);   cudaGetSymbolAddress((void**)&mid_lo, g_mid_lo);

    const int SM128 = 2 * (2*128*80 + 2*128*80);   // 81920
    const int SM64  = 2 * (2*128*80 + 2*64*80);    // 61440
    cudaFuncSetAttribute(gemm_mma<1,false,128>, cudaFuncAttributeMaxDynamicSharedMemorySize, SM128);
    cudaFuncSetAttribute(gemm_mma<0,false,128>, cudaFuncAttributeMaxDynamicSharedMemorySize, SM128);
    cudaFuncSetAttribute(gemm_mma<2,false,128>, cudaFuncAttributeMaxDynamicSharedMemorySize, SM128);
    cudaFuncSetAttribute(gemm_mma<3,false,128>, cudaFuncAttributeMaxDynamicSharedMemorySize, SM128);
    cudaFuncSetAttribute(gemm_mma<4,false,128>, cudaFuncAttributeMaxDynamicSharedMemorySize, SM128);
    cudaFuncSetAttribute(gemm_mma<1,true,64>,   cudaFuncAttributeMaxDynamicSharedMemorySize, SM64);

    // weight transpose + hi/lo split  (T is [N][K])
    tconv<<<dim3(QKVW/32, EMBED/32), dim3(32,8)>>>(w_qkv, wqkvT_hi, wqkvT_lo, EMBED, QKVW);
    tconv<<<dim3(EMBED/32, EMBED/32), dim3(32,8)>>>(w_out, woutT_hi, woutT_lo, EMBED, EMBED);
    tconv<<<dim3(MLPD/32, EMBED/32), dim3(32,8)>>>(w1, w1T_hi, w1T_lo, EMBED, MLPD);
    tconv<<<dim3(EMBED/32, MLPD/32), dim3(32,8)>>>(w2, w2T_hi, w2T_lo, MLPD, EMBED);

    // 1) h = LN1(x)
    ln_kernel<<<ROWS, 256>>>(x, ln1_g, ln1_b, h32, h_hi, h_lo);

    // 2) qkv = h @ w_qkv
    gemm_mma<1,false,128><<<dim3(QKVW/128, ROWS/128, 1), 256, SM128>>>(
        h_hi, h_lo, EMBED, 1, 0, 0,
        wqkvT_hi, wqkvT_lo, EMBED, 1, 0, 0,
        nullptr, qkv_hi, qkv_lo, QKVW, 1, 0, 0,
        nullptr, nullptr, nullptr, EMBED);

    // 3a) S = Q @ K^T  (batched over 48 heads)
    gemm_mma<0,false,128><<<dim3(SEQ/128, SEQ/128, BH), 256, SM128>>>(
        qkv_hi, qkv_lo, QKVW, HEADS, (size_t)SEQ*QKVW, HD,
        qkv_hi + EMBED, qkv_lo + EMBED, QKVW, HEADS, (size_t)SEQ*QKVW, HD,
        S, nullptr, nullptr, SEQ, BH, 0, (size_t)SEQ*SEQ,
        nullptr, nullptr, nullptr, HD);

    // 3b) P = softmax(S/8)
    softmax_k<<<BH*SEQ, 256>>>(S, P_hi, P_lo);

    // 3c) attn = P @ V  (V transposed in smem)
    gemm_mma<1,true,64><<<dim3(1, SEQ/128, BH), 256, SM64>>>(
        P_hi, P_lo, SEQ, BH, 0, (size_t)SEQ*SEQ,
        qkv_hi + 2*EMBED, qkv_lo + 2*EMBED, QKVW, HEADS, (size_t)SEQ*QKVW, HD,
        nullptr, attn_hi, attn_lo, EMBED, HEADS, (size_t)SEQ*EMBED, HD,
        nullptr, nullptr, nullptr, SEQ);

    // 4) x2 = x + h + attn @ w_out + b_out
    gemm_mma<2,false,128><<<dim3(EMBED/128, ROWS/128, 1), 256, SM128>>>(
        attn_hi, attn_lo, EMBED, 1, 0, 0,
        woutT_hi, woutT_lo, EMBED, 1, 0, 0,
        x2, nullptr, nullptr, EMBED, 1, 0, 0,
        b_out, x, h32, EMBED);

    // 5) h2 = LN2(x2)
    ln_kernel<<<ROWS, 256>>>(x2, ln2_g, ln2_b, nullptr, h2_hi, h2_lo);

    // 6) mid = gelu(h2 @ w1 + b1)
    gemm_mma<3,false,128><<<dim3(MLPD/128, ROWS/128, 1), 256, SM128>>>(
        h2_hi, h2_lo, EMBED, 1, 0, 0,
        w1T_hi, w1T_lo, EMBED, 1, 0, 0,
        nullptr, mid_hi, mid_lo, MLPD, 1, 0, 0,
        b1, nullptr, nullptr, EMBED);

    // 7) out = x2 + mid @ w2 + b2
    gemm_mma<4,false,128><<<dim3(EMBED/128, ROWS/128, 1), 256, SM128>>>(
        mid_hi, mid_lo, MLPD, 1, 0, 0,
        w2T_hi, w2T_lo, MLPD, 1, 0, 0,
        out, nullptr, nullptr, EMBED, 1, 0, 0,
        b2, x2, nullptr, MLPD);
}

// round 5
// speedup vs baseline: 3.4652x; 1.9702x over previous
#include <cuda_runtime.h>
#include <cuda_bf16.h>
#include <math.h>
#include <stdint.h>

#define EMBED 768
#define HEADS 12
#define HD    64
#define MLPD  3072
#define BATCH 4
#define SEQ   1024
#define ROWS  (BATCH*SEQ)
#define QKVW  (3*EMBED)
#define BH    (BATCH*HEADS)

typedef __nv_bfloat16 bf16;

// ------------------------- scratch ------------------------------------------
__device__ float g_h32 [ROWS*EMBED];
__device__ bf16  g_h_hi[ROWS*EMBED],  g_h_lo[ROWS*EMBED];
__device__ bf16  g_wqkvT_hi[QKVW*EMBED], g_wqkvT_lo[QKVW*EMBED];
__device__ bf16  g_woutT_hi[EMBED*EMBED], g_woutT_lo[EMBED*EMBED];
__device__ bf16  g_w1T_hi[MLPD*EMBED],  g_w1T_lo[MLPD*EMBED];
__device__ bf16  g_w2T_hi[EMBED*MLPD],  g_w2T_lo[EMBED*MLPD];
__device__ bf16  g_qkv_hi[ROWS*QKVW],   g_qkv_lo[ROWS*QKVW];
__device__ bf16  g_attn_hi[ROWS*EMBED], g_attn_lo[ROWS*EMBED];
__device__ float g_x2[ROWS*EMBED];
__device__ bf16  g_h2_hi[ROWS*EMBED],  g_h2_lo[ROWS*EMBED];
__device__ bf16  g_mid_hi[ROWS*MLPD],  g_mid_lo[ROWS*MLPD];

// ------------------------- helpers ------------------------------------------
__device__ __forceinline__ uint32_t smem_u32(const void* p){
    uint32_t a;
    asm("{ .reg .u64 t; cvta.to.shared.u64 t, %1; cvt.u32.u64 %0, t; }" : "=r"(a) : "l"(p));
    return a;
}
__device__ __forceinline__ void split_bf(float v, bf16& h, bf16& l){
    h = __float2bfloat16(v);
    l = __float2bfloat16(v - __bfloat162float(h));
}
__device__ __forceinline__ void cp16(uint32_t dst, const void* src){
    asm volatile("cp.async.cg.shared.global [%0], [%1], 16;" :: "r"(dst), "l"(src));
}
__device__ __forceinline__ void ldsm4(uint32_t* r, uint32_t a){
    asm volatile("ldmatrix.sync.aligned.m8n8.x4.shared.b16 {%0,%1,%2,%3}, [%4];"
        : "=r"(r[0]),"=r"(r[1]),"=r"(r[2]),"=r"(r[3]) : "r"(a));
}
__device__ __forceinline__ void ldsm4t(uint32_t* r, uint32_t a){
    asm volatile("ldmatrix.sync.aligned.m8n8.x4.trans.shared.b16 {%0,%1,%2,%3}, [%4];"
        : "=r"(r[0]),"=r"(r[1]),"=r"(r[2]),"=r"(r[3]) : "r"(a));
}
__device__ __forceinline__ void ldsm2(uint32_t* r, uint32_t a){
    asm volatile("ldmatrix.sync.aligned.m8n8.x2.shared.b16 {%0,%1}, [%2];"
        : "=r"(r[0]),"=r"(r[1]) : "r"(a));
}
__device__ __forceinline__ void mma16816(float* c, const uint32_t* a, const uint32_t* b){
    asm volatile("mma.sync.aligned.m16n8k16.row.col.f32.bf16.bf16.f32 "
        "{%0,%1,%2,%3}, {%4,%5,%6,%7}, {%8,%9}, {%0,%1,%2,%3};"
        : "+f"(c[0]),"+f"(c[1]),"+f"(c[2]),"+f"(c[3])
        : "r"(a[0]),"r"(a[1]),"r"(a[2]),"r"(a[3]), "r"(b[0]),"r"(b[1]));
}
__device__ __forceinline__ uint32_t pack_bf2(bf16 a, bf16 b){
    return (uint32_t)__bfloat16_as_ushort(a) | ((uint32_t)__bfloat16_as_ushort(b) << 16);
}
__device__ __forceinline__ void pack_split(float x, float y, uint32_t& hp, uint32_t& lp){
    bf16 hx, lx, hy, ly;
    split_bf(x, hx, lx); split_bf(y, hy, ly);
    hp = pack_bf2(hx, hy);
    lp = pack_bf2(lx, ly);
}

// ------------------------- weight transpose + split -------------------------
__global__ void tconv(const float* __restrict__ W, bf16* __restrict__ Thi, bf16* __restrict__ Tlo,
                      int K, int N)
{
    __shared__ float s[32][33];
    const int n0 = blockIdx.x * 32, k0 = blockIdx.y * 32;
    const int tx = threadIdx.x, ty = threadIdx.y;
    #pragma unroll
    for (int i = 0; i < 4; i++)
        s[ty + i*8][tx] = W[(size_t)(k0 + ty + i*8) * N + n0 + tx];
    __syncthreads();
    #pragma unroll
    for (int i = 0; i < 4; i++) {
        const int n = ty + i*8;
        float v = s[tx][n];
        bf16 h, l; split_bf(v, h, l);
        const size_t o = (size_t)(n0 + n) * K + k0 + tx;
        Thi[o] = h; Tlo[o] = l;
    }
}

// ------------------------- LayerNorm ----------------------------------------
__global__ __launch_bounds__(256) void ln_kernel(const float* __restrict__ x,
                                                 const float* __restrict__ g,
                                                 const float* __restrict__ b,
                                                 float* __restrict__ out32,
                                                 bf16* __restrict__ ohi,
                                                 bf16* __restrict__ olo)
{
    const int row = blockIdx.x;
    const int t = threadIdx.x;
    const float* xr = x + (size_t)row * EMBED;
    float v0 = xr[t], v1 = xr[t+256], v2 = xr[t+512];
    float s = v0+v1+v2, sq = v0*v0+v1*v1+v2*v2;
    #pragma unroll
    for (int off = 16; off; off >>= 1) {
        s  += __shfl_xor_sync(0xffffffffu, s,  off);
        sq += __shfl_xor_sync(0xffffffffu, sq, off);
    }
    __shared__ float red[16];
    const int w = t >> 5;
    if ((t & 31) == 0) { red[w] = s; red[8+w] = sq; }
    __syncthreads();
    float tot = 0.f, totq = 0.f;
    #pragma unroll
    for (int i = 0; i < 8; i++) { tot += red[i]; totq += red[8+i]; }
    const float mu = tot * (1.f/768.f);
    const float var = totq * (1.f/768.f) - mu*mu;
    const float rstd = rsqrtf(fmaxf(var, 0.f) + 1e-5f);
    const size_t o = (size_t)row * EMBED;
    #pragma unroll
    for (int i = 0; i < 3; i++) {
        const int c = t + i*256;
        const float v = (i==0?v0:(i==1?v1:v2));
        const float y = (v - mu) * rstd * g[c] + b[c];
        if (out32) out32[o + c] = y;
        bf16 h, l; split_bf(y, h, l);
        ohi[o + c] = h; olo[o + c] = l;
    }
}

// ------------------------- mma.sync hi/lo-split GEMM ------------------------
// C[m][n] = sum_k A[m][k]*B[n][k]; hi/lo planes; 3 MMAs (hh+hl+lh).
// Block 128x128, 8 warps (2m x 4n), warp 64x32, K-chunk 32, double-buffered.
// EPI 1: hi/lo split (QS: cols<768 scaled by 0.125 first)
// EPI 2: f32 +bias+add1+add2   EPI 3: split(gelu(+bias))   EPI 4: f32 +bias+add1
template<int EPI, bool QS>
__global__ void __launch_bounds__(256, 2) gemm_mma(
    const bf16* __restrict__ Ahi, const bf16* __restrict__ Alo, int lda,
    const bf16* __restrict__ Bhi, const bf16* __restrict__ Blo, int ldb,
    float* __restrict__ C, bf16* __restrict__ Chi, bf16* __restrict__ Clo, int ldc,
    const float* __restrict__ bias, const float* __restrict__ add1, const float* __restrict__ add2,
    int K)
{
    constexpr int RS  = 80;
    constexpr int SA  = 128 * RS;
    constexpr int BUF = 4 * SA;

    extern __shared__ char sm[];
    const uint32_t smb = smem_u32(sm);

    const int tid  = threadIdx.x;
    const int wid  = tid >> 5, lane = tid & 31;
    const int warp_m = wid & 1, warp_n = wid >> 1;
    const int rowBase = blockIdx.y * 128;
    const int colBase = blockIdx.x * 128;

    float acc[4][4][4];
    #pragma unroll
    for (int mt = 0; mt < 4; mt++)
        #pragma unroll
        for (int nt = 0; nt < 4; nt++)
            #pragma unroll
            for (int i = 0; i < 4; i++) acc[mt][nt][i] = 0.f;

    auto load_chunk = [&](int c) {
        const uint32_t st = smb + (c & 1)*BUF;
        const int k0 = c * 32;
        #pragma unroll
        for (int i = 0; i < 4; i++) {
            const int t = tid + i*256;
            const int plane = t >> 9, rr = (t >> 2) & 127, cg = t & 3;
            const bf16* src = (plane ? Alo : Ahi) + (size_t)(rowBase + rr) * lda + k0 + cg*8;
            cp16(st + plane*SA + rr*RS + cg*16, src);
        }
        #pragma unroll
        for (int i = 0; i < 4; i++) {
            const int t = tid + i*256;
            const int plane = t >> 9, rr = (t >> 2) & 127, cg = t & 3;
            const bf16* src = (plane ? Blo : Bhi) + (size_t)(colBase + rr) * ldb + k0 + cg*8;
            cp16(st + 2*SA + plane*SA + rr*RS + cg*16, src);
        }
        asm volatile("cp.async.commit_group;");
    };

    load_chunk(0);
    const int NC = K / 32;
    for (int c = 0; c < NC; ++c) {
        asm volatile("cp.async.wait_group 0;" ::: "memory");
        __syncthreads();
        if (c + 1 < NC) load_chunk(c + 1);

        const uint32_t st = smb + (c & 1)*BUF;
        #pragma unroll
        for (int ks = 0; ks < 2; ks++) {
            uint32_t bh[4][2], bl[4][2];
            #pragma unroll
            for (int nt = 0; nt < 4; nt++) {
                const int row = warp_n*32 + nt*8 + (lane & 7);
                const int kb  = ks*32 + ((lane >> 3) & 1)*16;
                const uint32_t ad = st + 2*SA + row*RS + kb;
                ldsm2(bh[nt], ad);
                ldsm2(bl[nt], ad + SA);
            }
            #pragma unroll
            for (int mt = 0; mt < 4; mt++) {
                const int row = warp_m*64 + mt*16 + (lane & 15);
                const int kb  = ks*32 + (lane >> 4)*16;
                const uint32_t aad = st + row*RS + kb;
                uint32_t ah[4], al[4];
                ldsm4(ah, aad);
                ldsm4(al, aad + SA);
                #pragma unroll
                for (int nt = 0; nt < 4; nt++) {
                    mma16816(acc[mt][nt], ah, bh[nt]);
                    mma16816(acc[mt][nt], ah, bl[nt]);
                    mma16816(acc[mt][nt], al, bh[nt]);
                }
            }
        }
    }

    #pragma unroll
    for (int mt = 0; mt < 4; mt++) {
        #pragma unroll
        for (int nt = 0; nt < 4; nt++) {
            const int gr0 = rowBase + warp_m*64 + mt*16 + (lane >> 2);
            const int gc  = colBase + warp_n*32 + nt*8 + (lane & 3)*2;
            #pragma unroll
            for (int half = 0; half < 2; half++) {
                const int gr = gr0 + half*8;
                const size_t idx = (size_t)gr * ldc + gc;
                float v0 = acc[mt][nt][half*2 + 0];
                float v1 = acc[mt][nt][half*2 + 1];
                if (EPI == 2) {
                    v0 += bias[gc+0] + add1[idx+0] + add2[idx+0];
                    v1 += bias[gc+1] + add1[idx+1] + add2[idx+1];
                    *(float2*)(C + idx) = make_float2(v0, v1);
                } else if (EPI == 4) {
                    v0 += bias[gc+0] + add1[idx+0];
                    v1 += bias[gc+1] + add1[idx+1];
                    *(float2*)(C + idx) = make_float2(v0, v1);
                } else {
                    if (EPI == 3) {
                        v0 += bias[gc+0];
                        v1 += bias[gc+1];
                        v0 = 0.5f * v0 * (1.f + erff(v0 * 0.70710678118654752f));
                        v1 = 0.5f * v1 * (1.f + erff(v1 * 0.70710678118654752f));
                    }
                    if (QS && gc < EMBED) { v0 *= 0.125f; v1 *= 0.125f; }
                    uint32_t hp, lp;
                    pack_split(v0, v1, hp, lp);
                    *(uint32_t*)(Chi + idx) = hp;
                    *(uint32_t*)(Clo + idx) = lp;
                }
            }
        }
    }
}

// ------------------------- fused flash attention ----------------------------
// grid (SEQ/128, BH), 256 thr = 8 warps x 16 query rows. KV tiles of 64 keys,
// double-buffered. S = Qh.Kh + Qh.Kl + Ql.Kh ; online softmax in regs; P hi/lo
// split re-used as A-fragments; V via ldmatrix.trans.
__global__ void __launch_bounds__(256) flash_attn(
    const bf16* __restrict__ qh_g, const bf16* __restrict__ ql_g,
    bf16* __restrict__ Ohi, bf16* __restrict__ Olo)
{
    // smem bytes: Qh 0, Ql 18432, KV buf b at 36864+b*36864:
    //   Kh +0, Kl +9216, Vh +18432, Vl +27648   (row stride 144B)
    extern __shared__ char sm[];
    const uint32_t smb = smem_u32(sm);
    const int tid = threadIdx.x, lane = tid & 31, wid = tid >> 5;
    const int qt = blockIdx.x;
    const int b  = blockIdx.y / HEADS, h = blockIdx.y % HEADS;
    const size_t gbase = (size_t)b * SEQ * QKVW;
    const int hoff = h * HD;

    #pragma unroll
    for (int i = 0; i < 8; i++) {
        const int t = tid + i*256;
        const int plane = t >> 10, rem = t & 1023, r = rem >> 3, cg = rem & 7;
        const bf16* src = (plane ? ql_g : qh_g) + gbase + (size_t)(qt*128 + r)*QKVW + hoff + cg*8;
        cp16(smb + plane*18432 + (uint32_t)(r*144 + cg*16), src);
    }
    auto load_kv = [&](int j) {
        const uint32_t dst = smb + 36864 + (j & 1)*36864;
        #pragma unroll
        for (int i = 0; i < 8; i++) {
            const int t = tid + i*256;
            const int q4 = t >> 9, rem = t & 511, r = rem >> 3, cg = rem & 7;
            const bf16* src = ((q4 & 1) ? ql_g : qh_g) + gbase
                + (size_t)(j*64 + r)*QKVW + EMBED + (q4 >> 1)*EMBED + hoff + cg*8;
            cp16(dst + (uint32_t)(q4*9216 + r*144 + cg*16), src);
        }
        asm volatile("cp.async.commit_group;");
    };
    load_kv(0);   // commits Q + KV0 together

    const int warprow = wid * 16;
    float m0 = -1e30f, m1 = -1e30f, l0 = 0.f, l1 = 0.f;
    float o[8][4];
    #pragma unroll
    for (int nt = 0; nt < 8; nt++)
        #pragma unroll
        for (int i = 0; i < 4; i++) o[nt][i] = 0.f;

    for (int j = 0; j < 16; j++) {
        asm volatile("cp.async.wait_group 0;" ::: "memory");
        __syncthreads();
        if (j < 15) load_kv(j + 1);
        const uint32_t st = smb + 36864 + (j & 1)*36864;

        // ---- S = Q K^T (scaled Q already) --------------------------------
        float s[8][4];
        #pragma unroll
        for (int nt = 0; nt < 8; nt++)
            #pragma unroll
            for (int i = 0; i < 4; i++) s[nt][i] = 0.f;
        #pragma unroll
        for (int ks = 0; ks < 4; ks++) {
            uint32_t qh[4], ql[4];
            const uint32_t qa = smb + (uint32_t)((warprow + (lane & 15))*144 + ks*32 + (lane >> 4)*16);
            ldsm4(qh, qa);
            ldsm4(ql, qa + 18432);
            #pragma unroll
            for (int nt = 0; nt < 8; nt++) {
                uint32_t kh[2], kl[2];
                const uint32_t ka = st + (uint32_t)((nt*8 + (lane & 7))*144 + ks*32 + ((lane >> 3) & 1)*16);
                ldsm2(kh, ka);
                ldsm2(kl, ka + 9216);
                mma16816(s[nt], qh, kh);
                mma16816(s[nt], qh, kl);
                mma16816(s[nt], ql, kh);
            }
        }

        // ---- online softmax ----------------------------------------------
        float mt0 = s[0][0], mt1 = s[0][2];
        #pragma unroll
        for (int nt = 0; nt < 8; nt++) {
            mt0 = fmaxf(mt0, fmaxf(s[nt][0], s[nt][1]));
            mt1 = fmaxf(mt1, fmaxf(s[nt][2], s[nt][3]));
        }
        mt0 = fmaxf(mt0, __shfl_xor_sync(0xffffffffu, mt0, 1));
        mt0 = fmaxf(mt0, __shfl_xor_sync(0xffffffffu, mt0, 2));
        mt1 = fmaxf(mt1, __shfl_xor_sync(0xffffffffu, mt1, 1));
        mt1 = fmaxf(mt1, __shfl_xor_sync(0xffffffffu, mt1, 2));
        const float mn0 = fmaxf(m0, mt0), mn1 = fmaxf(m1, mt1);
        const float a0 = __expf(m0 - mn0), a1 = __expf(m1 - mn1);
        float rs0 = 0.f, rs1 = 0.f;
        #pragma unroll
        for (int nt = 0; nt < 8; nt++) {
            s[nt][0] = __expf(s[nt][0] - mn0); rs0 += s[nt][0];
            s[nt][1] = __expf(s[nt][1] - mn0); rs0 += s[nt][1];
            s[nt][2] = __expf(s[nt][2] - mn1); rs1 += s[nt][2];
            s[nt][3] = __expf(s[nt][3] - mn1); rs1 += s[nt][3];
        }
        rs0 += __shfl_xor_sync(0xffffffffu, rs0, 1);
        rs0 += __shfl_xor_sync(0xffffffffu, rs0, 2);
        rs1 += __shfl_xor_sync(0xffffffffu, rs1, 1);
        rs1 += __shfl_xor_sync(0xffffffffu, rs1, 2);
        l0 = l0 * a0 + rs0;  l1 = l1 * a1 + rs1;
        m0 = mn0;  m1 = mn1;
        #pragma unroll
        for (int nt = 0; nt < 8; nt++) {
            o[nt][0] *= a0; o[nt][1] *= a0;
            o[nt][2] *= a1; o[nt][3] *= a1;
        }

        // ---- P fragments (hi/lo) -----------------------------------------
        uint32_t ph[4][4], pl[4][4];
        #pragma unroll
        for (int ks = 0; ks < 4; ks++) {
            pack_split(s[2*ks][0],   s[2*ks][1],   ph[ks][0], pl[ks][0]);
            pack_split(s[2*ks][2],   s[2*ks][3],   ph[ks][1], pl[ks][1]);
            pack_split(s[2*ks+1][0], s[2*ks+1][1], ph[ks][2], pl[ks][2]);
            pack_split(s[2*ks+1][2], s[2*ks+1][3], ph[ks][3], pl[ks][3]);
        }

        // ---- O += P V ----------------------------------------------------
        #pragma unroll
        for (int ks = 0; ks < 4; ks++) {
            #pragma unroll
            for (int ntp = 0; ntp < 4; ntp++) {
                uint32_t vh[4], vl[4];
                const uint32_t va = st + 18432
                    + (uint32_t)((ks*16 + ((lane >> 3) & 1)*8 + (lane & 7))*144
                                 + ntp*32 + (lane >> 4)*16);
                ldsm4t(vh, va);
                ldsm4t(vl, va + 9216);
                mma16816(o[2*ntp],   ph[ks], &vh[0]);
                mma16816(o[2*ntp],   ph[ks], &vl[0]);
                mma16816(o[2*ntp],   pl[ks], &vh[0]);
                mma16816(o[2*ntp+1], ph[ks], &vh[2]);
                mma16816(o[2*ntp+1], ph[ks], &vl[2]);
                mma16816(o[2*ntp+1], pl[ks], &vh[2]);
            }
        }
    }

    // ---- finalize + write ----------------------------------------------
    const float rl0 = 1.f / l0, rl1 = 1.f / l1;
    const int gr = b*SEQ + qt*128 + warprow + (lane >> 2);
    #pragma unroll
    for (int nt = 0; nt < 8; nt++) {
        const int gc = hoff + nt*8 + (lane & 3)*2;
        const size_t i0 = (size_t)gr * EMBED + gc;
        const size_t i1 = i0 + (size_t)8 * EMBED;
        uint32_t hp, lp;
        pack_split(o[nt][0]*rl0, o[nt][1]*rl0, hp, lp);
        *(uint32_t*)(Ohi + i0) = hp;  *(uint32_t*)(Olo + i0) = lp;
        pack_split(o[nt][2]*rl1, o[nt][3]*rl1, hp, lp);
        *(uint32_t*)(Ohi + i1) = hp;  *(uint32_t*)(Olo + i1) = lp;
    }
}

// ------------------------- host ---------------------------------------------
extern "C" void kernel_launch(void* const* d_in, const int* in_sizes, int n_in,
                              void* d_out, int out_size)
{
    const float* x     = (const float*)d_in[0];
    const float* ln1_g = (const float*)d_in[1];
    const float* ln1_b = (const float*)d_in[2];
    const float* w_qkv = (const float*)d_in[3];
    const float* w_out = (const float*)d_in[4];
    const float* b_out = (const float*)d_in[5];
    const float* ln2_g = (const float*)d_in[6];
    const float* ln2_b = (const float*)d_in[7];
    const float* w1    = (const float*)d_in[8];
    const float* b1    = (const float*)d_in[9];
    const float* w2    = (const float*)d_in[10];
    const float* b2    = (const float*)d_in[11];
    float* out = (float*)d_out;

    float *h32, *x2;
    bf16 *h_hi,*h_lo,*wqkvT_hi,*wqkvT_lo,*woutT_hi,*woutT_lo,*w1T_hi,*w1T_lo,*w2T_hi,*w2T_lo;
    bf16 *qkv_hi,*qkv_lo,*attn_hi,*attn_lo,*h2_hi,*h2_lo,*mid_hi,*mid_lo;
    cudaGetSymbolAddress((void**)&h32, g_h32);
    cudaGetSymbolAddress((void**)&h_hi, g_h_hi);       cudaGetSymbolAddress((void**)&h_lo, g_h_lo);
    cudaGetSymbolAddress((void**)&wqkvT_hi, g_wqkvT_hi); cudaGetSymbolAddress((void**)&wqkvT_lo, g_wqkvT_lo);
    cudaGetSymbolAddress((void**)&woutT_hi, g_woutT_hi); cudaGetSymbolAddress((void**)&woutT_lo, g_woutT_lo);
    cudaGetSymbolAddress((void**)&w1T_hi, g_w1T_hi);   cudaGetSymbolAddress((void**)&w1T_lo, g_w1T_lo);
    cudaGetSymbolAddress((void**)&w2T_hi, g_w2T_hi);   cudaGetSymbolAddress((void**)&w2T_lo, g_w2T_lo);
    cudaGetSymbolAddress((void**)&qkv_hi, g_qkv_hi);   cudaGetSymbolAddress((void**)&qkv_lo, g_qkv_lo);
    cudaGetSymbolAddress((void**)&attn_hi, g_attn_hi); cudaGetSymbolAddress((void**)&attn_lo, g_attn_lo);
    cudaGetSymbolAddress((void**)&x2, g_x2);
    cudaGetSymbolAddress((void**)&h2_hi, g_h2_hi);     cudaGetSymbolAddress((void**)&h2_lo, g_h2_lo);
    cudaGetSymbolAddress((void**)&mid_hi, g_mid_hi);   cudaGetSymbolAddress((void**)&mid_lo, g_mid_lo);

    const int SMG = 2 * 4 * 128 * 80;     // 81920
    const int SMF = 110592;
    cudaFuncSetAttribute(gemm_mma<1,true >, cudaFuncAttributeMaxDynamicSharedMemorySize, SMG);
    cudaFuncSetAttribute(gemm_mma<2,false>, cudaFuncAttributeMaxDynamicSharedMemorySize, SMG);
    cudaFuncSetAttribute(gemm_mma<3,false>, cudaFuncAttributeMaxDynamicSharedMemorySize, SMG);
    cudaFuncSetAttribute(gemm_mma<4,false>, cudaFuncAttributeMaxDynamicSharedMemorySize, SMG);
    cudaFuncSetAttribute(flash_attn,        cudaFuncAttributeMaxDynamicSharedMemorySize, SMF);

    tconv<<<dim3(QKVW/32, EMBED/32), dim3(32,8)>>>(w_qkv, wqkvT_hi, wqkvT_lo, EMBED, QKVW);
    tconv<<<dim3(EMBED/32, EMBED/32), dim3(32,8)>>>(w_out, woutT_hi, woutT_lo, EMBED, EMBED);
    tconv<<<dim3(MLPD/32, EMBED/32), dim3(32,8)>>>(w1, w1T_hi, w1T_lo, EMBED, MLPD);
    tconv<<<dim3(EMBED/32, MLPD/32), dim3(32,8)>>>(w2, w2T_hi, w2T_lo, MLPD, EMBED);

    // 1) h = LN1(x)
    ln_kernel<<<ROWS, 256>>>(x, ln1_g, ln1_b, h32, h_hi, h_lo);

    // 2) qkv = h @ w_qkv   (Q columns pre-scaled by 1/sqrt(64))
    gemm_mma<1,true><<<dim3(QKVW/128, ROWS/128), 256, SMG>>>(
        h_hi, h_lo, EMBED, wqkvT_hi, wqkvT_lo, EMBED,
        nullptr, qkv_hi, qkv_lo, QKVW, nullptr, nullptr, nullptr, EMBED);

    // 3) fused flash attention
    flash_attn<<<dim3(SEQ/128, BH), 256, SMF>>>(qkv_hi, qkv_lo, attn_hi, attn_lo);

    // 4) x2 = x + h + attn @ w_out + b_out
    gemm_mma<2,false><<<dim3(EMBED/128, ROWS/128), 256, SMG>>>(
        attn_hi, attn_lo, EMBED, woutT_hi, woutT_lo, EMBED,
        x2, nullptr, nullptr, EMBED, b_out, x, h32, EMBED);

    // 5) h2 = LN2(x2)
    ln_kernel<<<ROWS, 256>>>(x2, ln2_g, ln2_b, nullptr, h2_hi, h2_lo);

    // 6) mid = gelu(h2 @ w1 + b1)
    gemm_mma<3,false><<<dim3(MLPD/128, ROWS/128), 256, SMG>>>(
        h2_hi, h2_lo, EMBED, w1T_hi, w1T_lo, EMBED,
        nullptr, mid_hi, mid_lo, MLPD, b1, nullptr, nullptr, EMBED);

    // 7) out = x2 + mid @ w2 + b2
    gemm_mma<4,false><<<dim3(EMBED/128, ROWS/128), 256, SMG>>>(
        mid_hi, mid_lo, MLPD, w2T_hi, w2T_lo, MLPD,
        out, nullptr, nullptr, EMBED, b2, x2, nullptr, MLPD);
}